// round 15
// baseline (speedup 1.0000x reference)
#include <cuda_runtime.h>
#include <cuda_fp16.h>
#include <math.h>

// ---------------------------------------------------------------------------
// NonstationaryGaussianSpectralMixtureKernel
// Phase 1 (per point): u = A*cos(2pi ph), v = A*sin(2pi ph), s2 = s^2,
//   A = w*sqrt(s)*2^(1/4);  coords stored pre-scaled by sqrt(log2e).
// Phase 2: K[i,j] = sum_q (uX uY + vX vY) * [r * exp2(-d2*r)], r=1/(s2X+s2Y).
// Inner loop fully fp16x2 over j-pairs (HADD2/HFMA2/HMUL2); rcp via fp16
// magic seed + one Halley step (NO f16x2 MUFU rcp exists in PTX); exp2 on
// MUFU via ex2.approx.f16x2 (h2exp2).
// x-side smem: duplicated-half half2 (LDS.32 broadcast); y-side: j-pair half2.
// fp16 accumulation split even/odd q; fp32 only in the epilogue.
// pair_kernel: __launch_bounds__(256,5) -> <=48 regs -> ~62% occupancy.
// Phases linked by Programmatic Dependent Launch.
// ---------------------------------------------------------------------------

#define MAXPTS 8192
// [side][row][point]; rows: q->u, 8+q->v, 16+q->s2, 24..26 -> scaled coords
__device__ float g_feat[2][27][MAXPTS];

__device__ __forceinline__ float fex2_fast(float x) {
    float r; asm("ex2.approx.f32 %0, %1;" : "=f"(r) : "f"(x)); return r;
}
__device__ __forceinline__ float flg2_fast(float x) {
    float r; asm("lg2.approx.f32 %0, %1;" : "=f"(r) : "f"(x)); return r;
}

// fp16x2 reciprocal: per-half magic seed + one Halley step.
// Valid for s2 in [6e-5, ~24000] (no cross-half borrow, no subnormals).
__device__ __forceinline__ __half2 h2rcp_cubic(__half2 x) {
    unsigned int xb = *reinterpret_cast<unsigned int*>(&x);
    unsigned int rb = 0x779D779Du - xb;
    __half2 r0 = *reinterpret_cast<__half2*>(&rb);
    __half2 t  = __hmul2(x, r0);
    const __half2 h3  = __float2half2_rn(3.0f);
    const __half2 hn3 = __float2half2_rn(-3.0f);
    __half2 p  = __hfma2(t, t, __hfma2(hn3, t, h3));
    return __hmul2(r0, p);
}

__device__ __forceinline__ float selu_f(float x) {
    const float scale = 1.0507009873554805f;
    const float sa    = 1.7580993408473766f;   // scale*alpha
    const float LOG2E = 1.4426950408889634f;
    float em1 = fex2_fast(x * LOG2E) - 1.0f;
    return (x > 0.0f) ? scale * x : sa * em1;
}
__device__ __forceinline__ float softplus_f(float x) {
    const float LOG2E = 1.4426950408889634f;
    const float LN2   = 0.6931471805599453f;
    float e = fex2_fast(-fabsf(x) * LOG2E);
    return fmaxf(x, 0.0f) + LN2 * flg2_fast(1.0f + e);
}

// ---------------------------------------------------------------------------
// Phase 1: 8 threads per point (one per q), 32 points per 256-thread block.
// ---------------------------------------------------------------------------
__global__ void __launch_bounds__(256)
feat_kernel(
    const float* __restrict__ x, const float* __restrict__ y,
    const float* __restrict__ W1, const float* __restrict__ b1,
    const float* __restrict__ Ww, const float* __restrict__ bw,
    const float* __restrict__ Wf, const float* __restrict__ bf,
    const float* __restrict__ Ws, const float* __restrict__ bs,
    int N, int M)
{
    __shared__ float sW1[64 * 3];
    __shared__ float sb1[64];
    __shared__ float sHw[64][9];
    __shared__ float sHs[64][9];
    __shared__ float sHf[64][25];
    __shared__ float sbw[8], sbs[8], sbf[24];
    __shared__ float sh_h[32][65];

    int tid = threadIdx.x;
    for (int i = tid; i < 64 * 3; i += 256) sW1[i] = W1[i];
    for (int i = tid; i < 64;     i += 256) sb1[i] = b1[i];
    for (int i = tid; i < 8 * 64; i += 256) {
        int q = i >> 6, l = i & 63;
        sHw[l][q] = Ww[i];
        sHs[l][q] = Ws[i];
    }
    for (int i = tid; i < 24 * 64; i += 256) {
        int r = i >> 6, l = i & 63;
        sHf[l][r] = Wf[i];
    }
    if (tid < 8)  { sbw[tid] = bw[tid]; sbs[tid] = bs[tid]; }
    if (tid < 24) { sbf[tid] = bf[tid]; }
    __syncthreads();

    int pl    = tid >> 3;
    int lane8 = tid & 7;
    int pg    = blockIdx.x * 32 + pl;
    int total = N + M;

    float P0 = 0.0f, P1 = 0.0f, P2 = 0.0f;
    int side = 0, pt = 0;
    bool valid = (pg < total);
    if (valid) {
        side = (pg < N) ? 0 : 1;
        pt   = (pg < N) ? pg : pg - N;
        const float* P = (pg < N) ? (x + 3 * pg) : (y + 3 * (pg - N));
        P0 = P[0]; P1 = P[1]; P2 = P[2];
    }

    {
        int lbase = lane8 * 8;
#pragma unroll
        for (int k = 0; k < 8; k++) {
            int l = lbase + k;
            float t = sb1[l];
            t = fmaf(sW1[l * 3 + 0], P0, t);
            t = fmaf(sW1[l * 3 + 1], P1, t);
            t = fmaf(sW1[l * 3 + 2], P2, t);
            sh_h[pl][l] = selu_f(t);
        }
    }
    __syncthreads();

    if (valid) {
        int q = lane8;
        float aw = sbw[q], as = sbs[q];
        float f0 = sbf[q * 3 + 0], f1 = sbf[q * 3 + 1], f2 = sbf[q * 3 + 2];
#pragma unroll
        for (int l = 0; l < 64; l++) {
            float hl = sh_h[pl][l];
            aw = fmaf(sHw[l][q], hl, aw);
            as = fmaf(sHs[l][q], hl, as);
            f0 = fmaf(sHf[l][q * 3 + 0], hl, f0);
            f1 = fmaf(sHf[l][q * 3 + 1], hl, f1);
            f2 = fmaf(sHf[l][q * 3 + 2], hl, f2);
        }

        float w  = softplus_f(aw);
        float s  = softplus_f(as);
        float g0 = softplus_f(f0);
        float g1 = softplus_f(f1);
        float g2 = softplus_f(f2);
        float phase = g0 * P0 + g1 * P1 + g2 * P2;

        const float TWO_PI  = 6.283185307179586f;
        const float ROOT4_2 = 1.1892071150027210f;  // 2^(1/4)
        float ang = TWO_PI * phase;
        float sv = __sinf(ang);
        float cv = __cosf(ang);
        float A = w * sqrtf(s) * ROOT4_2;

        g_feat[side][q][pt]      = A * cv;
        g_feat[side][8 + q][pt]  = A * sv;
        g_feat[side][16 + q][pt] = s * s;

        if (q == 0) {
            const float SQRT_LOG2E = 1.2011224087864498f;  // sqrt(log2(e))
            g_feat[side][24][pt] = P0 * SQRT_LOG2E;
            g_feat[side][25][pt] = P1 * SQRT_LOG2E;
            g_feat[side][26][pt] = P2 * SQRT_LOG2E;
        }
    }

    // PDL: all stores done; let the dependent pair_kernel proceed.
    asm volatile("griddepcontrol.launch_dependents;");
}

// ---------------------------------------------------------------------------
// Phase 2: pair kernel. 64x64 tile per 256-thread block, 4x4 micro-tile.
// Fully packed fp16x2 inner loop; min 5 blocks/SM for latency hiding.
// ---------------------------------------------------------------------------
__global__ void __launch_bounds__(256, 5)
pair_kernel(float* __restrict__ out, int N, int M)
{
    __shared__ __half2 sbx[24][64];   // x feats, value duplicated in both halves
    __shared__ __half2 sby[24][32];   // y feats, packed j-pairs
    __shared__ float   scx[3][64];    // x scaled coords (fp32)
    __shared__ float   scy[3][64];    // y scaled coords (fp32)

    // PDL: wait for feat_kernel's g_feat stores to be visible.
    asm volatile("griddepcontrol.wait;");

    int tid = threadIdx.x;
    int i0 = blockIdx.y * 64;
    int j0 = blockIdx.x * 64;

    // x-side: broadcast-packed half2
    for (int idx = tid; idx < 24 * 64; idx += 256) {
        int r = idx >> 6, c = idx & 63;
        float pad = (r >= 16) ? 1.0f : 0.0f;
        int gi = i0 + c;
        float v = (gi < N) ? g_feat[0][r][gi] : pad;
        sbx[r][c] = __half2half2(__float2half_rn(v));
    }
    // y-side: j-pair-packed half2  (24 rows x 32 pairs)
    for (int idx = tid; idx < 24 * 32; idx += 256) {
        int r = idx >> 5, c = idx & 31;
        float pad = (r >= 16) ? 1.0f : 0.0f;
        int gj = j0 + 2 * c;
        float a = (gj     < M) ? g_feat[1][r][gj]     : pad;
        float b = (gj + 1 < M) ? g_feat[1][r][gj + 1] : pad;
        sby[r][c] = __floats2half2_rn(a, b);
    }
    for (int idx = tid; idx < 3 * 64; idx += 256) {
        int d = idx >> 6, c = idx & 63;
        int gi = i0 + c;
        scx[d][c] = (gi < N) ? g_feat[0][24 + d][gi] : 0.0f;
        int gj = j0 + c;
        scy[d][c] = (gj < M) ? g_feat[1][24 + d][gj] : 0.0f;
    }
    __syncthreads();

    int tx = tid & 15;      // j group
    int ty = tid >> 4;      // i group
    int ib = ty * 4;
    int jb = tx * 4;

    // d2h[ii][jp] = half2{-d2(ii,2jp), -d2(ii,2jp+1)}  (log2e in coords)
    __half2 d2h[4][2];
    {
        float4 px0 = *(const float4*)&scx[0][ib];
        float4 px1 = *(const float4*)&scx[1][ib];
        float4 px2 = *(const float4*)&scx[2][ib];
        float4 py0 = *(const float4*)&scy[0][jb];
        float4 py1 = *(const float4*)&scy[1][jb];
        float4 py2 = *(const float4*)&scy[2][jb];

        float xa0[4] = {px0.x, px0.y, px0.z, px0.w};
        float xa1[4] = {px1.x, px1.y, px1.z, px1.w};
        float xa2[4] = {px2.x, px2.y, px2.z, px2.w};
        float ya0[4] = {py0.x, py0.y, py0.z, py0.w};
        float ya1[4] = {py1.x, py1.y, py1.z, py1.w};
        float ya2[4] = {py2.x, py2.y, py2.z, py2.w};

#pragma unroll
        for (int ii = 0; ii < 4; ii++) {
            float t[4];
#pragma unroll
            for (int jj = 0; jj < 4; jj++) {
                float dx = xa0[ii] - ya0[jj];
                float dy = xa1[ii] - ya1[jj];
                float dz = xa2[ii] - ya2[jj];
                t[jj] = -fmaf(dx, dx, fmaf(dy, dy, dz * dz));
            }
            d2h[ii][0] = __floats2half2_rn(t[0], t[1]);
            d2h[ii][1] = __floats2half2_rn(t[2], t[3]);
        }
    }

    // fp16 accumulators, split even/odd q
    __half2 accA[4][2], accB[4][2];
#pragma unroll
    for (int ii = 0; ii < 4; ii++)
#pragma unroll
        for (int jp = 0; jp < 2; jp++) {
            accA[ii][jp] = __float2half2_rn(0.0f);
            accB[ii][jp] = __float2half2_rn(0.0f);
        }

#pragma unroll
    for (int q = 0; q < 8; q++) {
        __half2 uyh[2] = {sby[q][tx * 2],      sby[q][tx * 2 + 1]};
        __half2 vyh[2] = {sby[8 + q][tx * 2],  sby[8 + q][tx * 2 + 1]};
        __half2 wyh[2] = {sby[16 + q][tx * 2], sby[16 + q][tx * 2 + 1]};

#pragma unroll
        for (int ii = 0; ii < 4; ii++) {
            __half2 uxh = sbx[q][ib + ii];       // LDS.32 broadcast pair
            __half2 vxh = sbx[8 + q][ib + ii];
            __half2 wxh = sbx[16 + q][ib + ii];

#pragma unroll
            for (int jp = 0; jp < 2; jp++) {
                __half2 s2h = __hadd2(wxh, wyh[jp]);
                __half2 rh  = h2rcp_cubic(s2h);            // fp16 Halley
                __half2 zh  = __hmul2(d2h[ii][jp], rh);
                __half2 eh  = h2exp2(zh);                  // MUFU f16x2
                __half2 reh = __hmul2(rh, eh);
                __half2 cch = __hfma2(uxh, uyh[jp], __hmul2(vxh, vyh[jp]));
                if (q & 1) accB[ii][jp] = __hfma2(cch, reh, accB[ii][jp]);
                else       accA[ii][jp] = __hfma2(cch, reh, accA[ii][jp]);
            }
        }
    }

    // epilogue: fp16 partials -> fp32, store
#pragma unroll
    for (int ii = 0; ii < 4; ii++) {
        int i = i0 + ib + ii;
        if (i >= N) continue;
        float2 a0 = __half22float2(accA[ii][0]);
        float2 b0 = __half22float2(accB[ii][0]);
        float2 a1 = __half22float2(accA[ii][1]);
        float2 b1 = __half22float2(accB[ii][1]);
        float r0 = a0.x + b0.x, r1 = a0.y + b0.y;
        float r2 = a1.x + b1.x, r3 = a1.y + b1.y;
        int j = j0 + jb;
        if (j + 3 < M) {
            *(float4*)&out[(size_t)i * M + j] = make_float4(r0, r1, r2, r3);
        } else {
            float av[4] = {r0, r1, r2, r3};
#pragma unroll
            for (int jj = 0; jj < 4; jj++)
                if (j + jj < M) out[(size_t)i * M + j + jj] = av[jj];
        }
    }
}

// ---------------------------------------------------------------------------
extern "C" void kernel_launch(void* const* d_in, const int* in_sizes, int n_in,
                              void* d_out, int out_size) {
    const float* x  = (const float*)d_in[0];
    const float* y  = (const float*)d_in[1];
    const float* W1 = (const float*)d_in[2];
    const float* b1 = (const float*)d_in[3];
    const float* Ww = (const float*)d_in[4];
    const float* bw = (const float*)d_in[5];
    const float* Wf = (const float*)d_in[6];
    const float* bf = (const float*)d_in[7];
    const float* Ws = (const float*)d_in[8];
    const float* bs = (const float*)d_in[9];
    float* out = (float*)d_out;

    int N = in_sizes[0] / 3;
    int M = in_sizes[1] / 3;

    int total = N + M;
    feat_kernel<<<(total + 31) / 32, 256>>>(x, y, W1, b1, Ww, bw, Wf, bf,
                                            Ws, bs, N, M);

    dim3 grid((M + 63) / 64, (N + 63) / 64);
    cudaLaunchConfig_t cfg = {};
    cfg.gridDim  = grid;
    cfg.blockDim = dim3(256, 1, 1);
    cfg.dynamicSmemBytes = 0;
    cfg.stream = 0;
    cudaLaunchAttribute attrs[1];
    attrs[0].id = cudaLaunchAttributeProgrammaticStreamSerialization;
    attrs[0].val.programmaticStreamSerializationAllowed = 1;
    cfg.attrs = attrs;
    cfg.numAttrs = 1;
    cudaLaunchKernelEx(&cfg, pair_kernel, out, N, M);
}

// round 16
// speedup vs baseline: 1.0042x; 1.0042x over previous
#include <cuda_runtime.h>
#include <cuda_fp16.h>
#include <math.h>

// ---------------------------------------------------------------------------
// NonstationaryGaussianSpectralMixtureKernel
// Phase 1 (per point): u = A*cos(2pi ph), v = A*sin(2pi ph), s2 = s^2,
//   A = w*sqrt(s)*2^(1/4);  coords stored pre-scaled by sqrt(log2e).
// Phase 2: K[i,j] = sum_q (uX uY + vX vY) * [r * exp2(-d2*r)], r=1/(s2X+s2Y).
// Inner loop fully fp16x2 over j-pairs; rcp via fp16 magic+Halley (no f16x2
// MUFU rcp exists); exp2 via ex2.approx.f16x2 (MUFU).
// Shared loads VECTORIZED: x-side 3x LDS.128 per q (broadcast-packed half2),
// y-side 3x LDS.64 per q (j-pair-packed half2) -> 48 LDS/thread (was 144).
// fp16 accumulation split even/odd q; fp32 only in the epilogue.
// Phases linked by Programmatic Dependent Launch.
// ---------------------------------------------------------------------------

#define MAXPTS 8192
// [side][row][point]; rows: q->u, 8+q->v, 16+q->s2, 24..26 -> scaled coords
__device__ float g_feat[2][27][MAXPTS];

__device__ __forceinline__ float fex2_fast(float x) {
    float r; asm("ex2.approx.f32 %0, %1;" : "=f"(r) : "f"(x)); return r;
}
__device__ __forceinline__ float flg2_fast(float x) {
    float r; asm("lg2.approx.f32 %0, %1;" : "=f"(r) : "f"(x)); return r;
}
__device__ __forceinline__ __half2 u2h2(unsigned int u) {
    __half2 h; *reinterpret_cast<unsigned int*>(&h) = u; return h;
}

// fp16x2 reciprocal: per-half magic seed + one Halley step.
// Valid for s2 in [6e-5, ~24000] (no cross-half borrow, no subnormals).
__device__ __forceinline__ __half2 h2rcp_cubic(__half2 x) {
    unsigned int xb = *reinterpret_cast<unsigned int*>(&x);
    unsigned int rb = 0x779D779Du - xb;
    __half2 r0 = *reinterpret_cast<__half2*>(&rb);
    __half2 t  = __hmul2(x, r0);
    const __half2 h3  = __float2half2_rn(3.0f);
    const __half2 hn3 = __float2half2_rn(-3.0f);
    __half2 p  = __hfma2(t, t, __hfma2(hn3, t, h3));
    return __hmul2(r0, p);
}

__device__ __forceinline__ float selu_f(float x) {
    const float scale = 1.0507009873554805f;
    const float sa    = 1.7580993408473766f;   // scale*alpha
    const float LOG2E = 1.4426950408889634f;
    float em1 = fex2_fast(x * LOG2E) - 1.0f;
    return (x > 0.0f) ? scale * x : sa * em1;
}
__device__ __forceinline__ float softplus_f(float x) {
    const float LOG2E = 1.4426950408889634f;
    const float LN2   = 0.6931471805599453f;
    float e = fex2_fast(-fabsf(x) * LOG2E);
    return fmaxf(x, 0.0f) + LN2 * flg2_fast(1.0f + e);
}

// ---------------------------------------------------------------------------
// Phase 1: 8 threads per point (one per q), 32 points per 256-thread block.
// ---------------------------------------------------------------------------
__global__ void __launch_bounds__(256)
feat_kernel(
    const float* __restrict__ x, const float* __restrict__ y,
    const float* __restrict__ W1, const float* __restrict__ b1,
    const float* __restrict__ Ww, const float* __restrict__ bw,
    const float* __restrict__ Wf, const float* __restrict__ bf,
    const float* __restrict__ Ws, const float* __restrict__ bs,
    int N, int M)
{
    __shared__ float sW1[64 * 3];
    __shared__ float sb1[64];
    __shared__ float sHw[64][9];
    __shared__ float sHs[64][9];
    __shared__ float sHf[64][25];
    __shared__ float sbw[8], sbs[8], sbf[24];
    __shared__ float sh_h[32][65];

    int tid = threadIdx.x;
    for (int i = tid; i < 64 * 3; i += 256) sW1[i] = W1[i];
    for (int i = tid; i < 64;     i += 256) sb1[i] = b1[i];
    for (int i = tid; i < 8 * 64; i += 256) {
        int q = i >> 6, l = i & 63;
        sHw[l][q] = Ww[i];
        sHs[l][q] = Ws[i];
    }
    for (int i = tid; i < 24 * 64; i += 256) {
        int r = i >> 6, l = i & 63;
        sHf[l][r] = Wf[i];
    }
    if (tid < 8)  { sbw[tid] = bw[tid]; sbs[tid] = bs[tid]; }
    if (tid < 24) { sbf[tid] = bf[tid]; }
    __syncthreads();

    int pl    = tid >> 3;
    int lane8 = tid & 7;
    int pg    = blockIdx.x * 32 + pl;
    int total = N + M;

    float P0 = 0.0f, P1 = 0.0f, P2 = 0.0f;
    int side = 0, pt = 0;
    bool valid = (pg < total);
    if (valid) {
        side = (pg < N) ? 0 : 1;
        pt   = (pg < N) ? pg : pg - N;
        const float* P = (pg < N) ? (x + 3 * pg) : (y + 3 * (pg - N));
        P0 = P[0]; P1 = P[1]; P2 = P[2];
    }

    {
        int lbase = lane8 * 8;
#pragma unroll
        for (int k = 0; k < 8; k++) {
            int l = lbase + k;
            float t = sb1[l];
            t = fmaf(sW1[l * 3 + 0], P0, t);
            t = fmaf(sW1[l * 3 + 1], P1, t);
            t = fmaf(sW1[l * 3 + 2], P2, t);
            sh_h[pl][l] = selu_f(t);
        }
    }
    __syncthreads();

    if (valid) {
        int q = lane8;
        float aw = sbw[q], as = sbs[q];
        float f0 = sbf[q * 3 + 0], f1 = sbf[q * 3 + 1], f2 = sbf[q * 3 + 2];
#pragma unroll
        for (int l = 0; l < 64; l++) {
            float hl = sh_h[pl][l];
            aw = fmaf(sHw[l][q], hl, aw);
            as = fmaf(sHs[l][q], hl, as);
            f0 = fmaf(sHf[l][q * 3 + 0], hl, f0);
            f1 = fmaf(sHf[l][q * 3 + 1], hl, f1);
            f2 = fmaf(sHf[l][q * 3 + 2], hl, f2);
        }

        float w  = softplus_f(aw);
        float s  = softplus_f(as);
        float g0 = softplus_f(f0);
        float g1 = softplus_f(f1);
        float g2 = softplus_f(f2);
        float phase = g0 * P0 + g1 * P1 + g2 * P2;

        const float TWO_PI  = 6.283185307179586f;
        const float ROOT4_2 = 1.1892071150027210f;  // 2^(1/4)
        float ang = TWO_PI * phase;
        float sv = __sinf(ang);
        float cv = __cosf(ang);
        float A = w * sqrtf(s) * ROOT4_2;

        g_feat[side][q][pt]      = A * cv;
        g_feat[side][8 + q][pt]  = A * sv;
        g_feat[side][16 + q][pt] = s * s;

        if (q == 0) {
            const float SQRT_LOG2E = 1.2011224087864498f;  // sqrt(log2(e))
            g_feat[side][24][pt] = P0 * SQRT_LOG2E;
            g_feat[side][25][pt] = P1 * SQRT_LOG2E;
            g_feat[side][26][pt] = P2 * SQRT_LOG2E;
        }
    }

    // PDL: all stores done; let the dependent pair_kernel proceed.
    asm volatile("griddepcontrol.launch_dependents;");
}

// ---------------------------------------------------------------------------
// Phase 2: pair kernel. 64x64 tile per 256-thread block, 4x4 micro-tile.
// Fully packed fp16x2 inner loop with vectorized shared loads.
// ---------------------------------------------------------------------------
__global__ void __launch_bounds__(256)
pair_kernel(float* __restrict__ out, int N, int M)
{
    __shared__ __half2 sbx[24][64];   // x feats, value duplicated in both halves
    __shared__ __half2 sby[24][32];   // y feats, packed j-pairs
    __shared__ float   scx[3][64];    // x scaled coords (fp32)
    __shared__ float   scy[3][64];    // y scaled coords (fp32)

    // PDL: wait for feat_kernel's g_feat stores to be visible.
    asm volatile("griddepcontrol.wait;");

    int tid = threadIdx.x;
    int i0 = blockIdx.y * 64;
    int j0 = blockIdx.x * 64;

    // x-side: broadcast-packed half2
    for (int idx = tid; idx < 24 * 64; idx += 256) {
        int r = idx >> 6, c = idx & 63;
        float pad = (r >= 16) ? 1.0f : 0.0f;
        int gi = i0 + c;
        float v = (gi < N) ? g_feat[0][r][gi] : pad;
        sbx[r][c] = __half2half2(__float2half_rn(v));
    }
    // y-side: j-pair-packed half2  (24 rows x 32 pairs)
    for (int idx = tid; idx < 24 * 32; idx += 256) {
        int r = idx >> 5, c = idx & 31;
        float pad = (r >= 16) ? 1.0f : 0.0f;
        int gj = j0 + 2 * c;
        float a = (gj     < M) ? g_feat[1][r][gj]     : pad;
        float b = (gj + 1 < M) ? g_feat[1][r][gj + 1] : pad;
        sby[r][c] = __floats2half2_rn(a, b);
    }
    for (int idx = tid; idx < 3 * 64; idx += 256) {
        int d = idx >> 6, c = idx & 63;
        int gi = i0 + c;
        scx[d][c] = (gi < N) ? g_feat[0][24 + d][gi] : 0.0f;
        int gj = j0 + c;
        scy[d][c] = (gj < M) ? g_feat[1][24 + d][gj] : 0.0f;
    }
    __syncthreads();

    int tx = tid & 15;      // j group
    int ty = tid >> 4;      // i group
    int ib = ty * 4;        // multiple of 4 -> &sbx[r][ib] is 16B-aligned
    int jb = tx * 4;

    // d2h[ii][jp] = half2{-d2(ii,2jp), -d2(ii,2jp+1)}  (log2e in coords)
    __half2 d2h[4][2];
    {
        float4 px0 = *(const float4*)&scx[0][ib];
        float4 px1 = *(const float4*)&scx[1][ib];
        float4 px2 = *(const float4*)&scx[2][ib];
        float4 py0 = *(const float4*)&scy[0][jb];
        float4 py1 = *(const float4*)&scy[1][jb];
        float4 py2 = *(const float4*)&scy[2][jb];

        float xa0[4] = {px0.x, px0.y, px0.z, px0.w};
        float xa1[4] = {px1.x, px1.y, px1.z, px1.w};
        float xa2[4] = {px2.x, px2.y, px2.z, px2.w};
        float ya0[4] = {py0.x, py0.y, py0.z, py0.w};
        float ya1[4] = {py1.x, py1.y, py1.z, py1.w};
        float ya2[4] = {py2.x, py2.y, py2.z, py2.w};

#pragma unroll
        for (int ii = 0; ii < 4; ii++) {
            float t[4];
#pragma unroll
            for (int jj = 0; jj < 4; jj++) {
                float dx = xa0[ii] - ya0[jj];
                float dy = xa1[ii] - ya1[jj];
                float dz = xa2[ii] - ya2[jj];
                t[jj] = -fmaf(dx, dx, fmaf(dy, dy, dz * dz));
            }
            d2h[ii][0] = __floats2half2_rn(t[0], t[1]);
            d2h[ii][1] = __floats2half2_rn(t[2], t[3]);
        }
    }

    // fp16 accumulators, split even/odd q
    __half2 accA[4][2], accB[4][2];
#pragma unroll
    for (int ii = 0; ii < 4; ii++)
#pragma unroll
        for (int jp = 0; jp < 2; jp++) {
            accA[ii][jp] = __float2half2_rn(0.0f);
            accB[ii][jp] = __float2half2_rn(0.0f);
        }

#pragma unroll
    for (int q = 0; q < 8; q++) {
        // x-side: one LDS.128 per feature row -> all 4 ii values
        uint4 uxu = *(const uint4*)&sbx[q][ib];
        uint4 vxu = *(const uint4*)&sbx[8 + q][ib];
        uint4 wxu = *(const uint4*)&sbx[16 + q][ib];
        unsigned int uxa[4] = {uxu.x, uxu.y, uxu.z, uxu.w};
        unsigned int vxa[4] = {vxu.x, vxu.y, vxu.z, vxu.w};
        unsigned int wxa[4] = {wxu.x, wxu.y, wxu.z, wxu.w};

        // y-side: one LDS.64 per feature row -> both jp pairs
        uint2 uyu = *(const uint2*)&sby[q][tx * 2];
        uint2 vyu = *(const uint2*)&sby[8 + q][tx * 2];
        uint2 wyu = *(const uint2*)&sby[16 + q][tx * 2];
        __half2 uyh[2] = {u2h2(uyu.x), u2h2(uyu.y)};
        __half2 vyh[2] = {u2h2(vyu.x), u2h2(vyu.y)};
        __half2 wyh[2] = {u2h2(wyu.x), u2h2(wyu.y)};

#pragma unroll
        for (int ii = 0; ii < 4; ii++) {
            __half2 uxh = u2h2(uxa[ii]);
            __half2 vxh = u2h2(vxa[ii]);
            __half2 wxh = u2h2(wxa[ii]);

#pragma unroll
            for (int jp = 0; jp < 2; jp++) {
                __half2 s2h = __hadd2(wxh, wyh[jp]);
                __half2 rh  = h2rcp_cubic(s2h);            // fp16 Halley
                __half2 zh  = __hmul2(d2h[ii][jp], rh);
                __half2 eh  = h2exp2(zh);                  // MUFU f16x2
                __half2 reh = __hmul2(rh, eh);
                __half2 cch = __hfma2(uxh, uyh[jp], __hmul2(vxh, vyh[jp]));
                if (q & 1) accB[ii][jp] = __hfma2(cch, reh, accB[ii][jp]);
                else       accA[ii][jp] = __hfma2(cch, reh, accA[ii][jp]);
            }
        }
    }

    // epilogue: fp16 partials -> fp32, store
#pragma unroll
    for (int ii = 0; ii < 4; ii++) {
        int i = i0 + ib + ii;
        if (i >= N) continue;
        float2 a0 = __half22float2(accA[ii][0]);
        float2 b0 = __half22float2(accB[ii][0]);
        float2 a1 = __half22float2(accA[ii][1]);
        float2 b1 = __half22float2(accB[ii][1]);
        float r0 = a0.x + b0.x, r1 = a0.y + b0.y;
        float r2 = a1.x + b1.x, r3 = a1.y + b1.y;
        int j = j0 + jb;
        if (j + 3 < M) {
            *(float4*)&out[(size_t)i * M + j] = make_float4(r0, r1, r2, r3);
        } else {
            float av[4] = {r0, r1, r2, r3};
#pragma unroll
            for (int jj = 0; jj < 4; jj++)
                if (j + jj < M) out[(size_t)i * M + j + jj] = av[jj];
        }
    }
}

// ---------------------------------------------------------------------------
extern "C" void kernel_launch(void* const* d_in, const int* in_sizes, int n_in,
                              void* d_out, int out_size) {
    const float* x  = (const float*)d_in[0];
    const float* y  = (const float*)d_in[1];
    const float* W1 = (const float*)d_in[2];
    const float* b1 = (const float*)d_in[3];
    const float* Ww = (const float*)d_in[4];
    const float* bw = (const float*)d_in[5];
    const float* Wf = (const float*)d_in[6];
    const float* bf = (const float*)d_in[7];
    const float* Ws = (const float*)d_in[8];
    const float* bs = (const float*)d_in[9];
    float* out = (float*)d_out;

    int N = in_sizes[0] / 3;
    int M = in_sizes[1] / 3;

    int total = N + M;
    feat_kernel<<<(total + 31) / 32, 256>>>(x, y, W1, b1, Ww, bw, Wf, bf,
                                            Ws, bs, N, M);

    dim3 grid((M + 63) / 64, (N + 63) / 64);
    cudaLaunchConfig_t cfg = {};
    cfg.gridDim  = grid;
    cfg.blockDim = dim3(256, 1, 1);
    cfg.dynamicSmemBytes = 0;
    cfg.stream = 0;
    cudaLaunchAttribute attrs[1];
    attrs[0].id = cudaLaunchAttributeProgrammaticStreamSerialization;
    attrs[0].val.programmaticStreamSerializationAllowed = 1;
    cfg.attrs = attrs;
    cfg.numAttrs = 1;
    cudaLaunchKernelEx(&cfg, pair_kernel, out, N, M);
}